// round 7
// baseline (speedup 1.0000x reference)
#include <cuda_runtime.h>
#include <cuda_bf16.h>
#include <math.h>
#include <stdint.h>

#define NN 100000
#define EE 1600000
#define NB ((NN + 255) / 256)   // 391 scan blocks
#define NPAD (NN + 128)

// ---------------- scratch (device globals; no allocs allowed) ----------------
__device__ int   g_cnt[NN];
__device__ int   g_rowptr[NN + 1];
__device__ int   g_blk[512];
__device__ int   g_cursor[NN];
__device__ int   g_ecol[EE];
__device__ float g_ew[EE];
__device__ float g_sp2[2][NN];
__device__ float g_p3 [2][NN];
__device__ float g_wself[NN];
__device__ float g_h  [(size_t)NPAD * 128];
__device__ float g_agg[(size_t)NPAD * 128];
// W pre-packed in m16n8k16 B-fragment layout: uint2 per (kstep, ntile, lane)
//   .x = bf16x2 {W[k0+2q][n], W[k0+2q+1][n]},  .y = same +8 in k
//   q = lane&3, n = ntile*8 + (lane>>2), k0 = kstep*16
__device__ uint2 g_wf1hi[8 * 16 * 32], g_wf1lo[8 * 16 * 32];
__device__ uint2 g_wf2hi[8 * 16 * 32], g_wf2lo[8 * 16 * 32];
__device__ uint2 g_wf3hi[8 *  8 * 32], g_wf3lo[8 *  8 * 32];

// ---------------- helpers ----------------
__device__ __forceinline__ uint32_t smem_u32(const void* p) {
    uint32_t a;
    asm("{ .reg .u64 t; cvta.to.shared.u64 t, %1; cvt.u32.u64 %0, t; }" : "=r"(a) : "l"(p));
    return a;
}
__device__ __forceinline__ float zpow(float d, float e) {
    float p = powf(d, e);
    return isinf(p) ? 0.0f : p;
}
__device__ __forceinline__ uint32_t pack_bf2(float a, float b) {
    __nv_bfloat162 t = __floats2bfloat162_rn(a, b);
    return *reinterpret_cast<uint32_t*>(&t);
}

#define LDSM_X4(r0, r1, r2, r3, addr)                                          \
    asm volatile("ldmatrix.sync.aligned.m8n8.x4.shared.b16 {%0,%1,%2,%3}, [%4];" \
                 : "=r"(r0), "=r"(r1), "=r"(r2), "=r"(r3) : "r"(addr))

__device__ __forceinline__ void mma16816(float* d, const uint32_t* a,
                                         uint32_t b0, uint32_t b1) {
    asm volatile(
        "mma.sync.aligned.m16n8k16.row.col.f32.bf16.bf16.f32 "
        "{%0,%1,%2,%3}, {%4,%5,%6,%7}, {%8,%9}, {%0,%1,%2,%3};"
        : "+f"(d[0]), "+f"(d[1]), "+f"(d[2]), "+f"(d[3])
        : "r"(a[0]), "r"(a[1]), "r"(a[2]), "r"(a[3]), "r"(b0), "r"(b1));
}

// ---------------- GSO / CSR build ----------------
__global__ void zero_cnt_kernel() {
    int i = blockIdx.x * blockDim.x + threadIdx.x;
    if (i < NN) g_cnt[i] = 0;
}

__global__ void deg_count_kernel(const int* __restrict__ row) {
    int e = blockIdx.x * blockDim.x + threadIdx.x;
    if (e < EE) atomicAdd(&g_cnt[row[e]], 1);
}

// fused: block-local exclusive scan of g_cnt AND node GSO weights
__global__ void scan_a_nw_kernel(const float* __restrict__ p1,
                                 const float* __restrict__ p2) {
    __shared__ int s[256];
    int tid = threadIdx.x;
    int i = blockIdx.x * 256 + tid;
    int v = (i < NN) ? g_cnt[i] : 0;
    s[tid] = v;

    // node weights (independent math, overlaps the scan barriers)
    if (i < NN) {
        float deg = (float)v;
        float ws = 0.0f;
        const float* ps[2] = {p1, p2};
        #pragma unroll
        for (int g = 0; g < 2; g++) {
            float m1 = ps[g][0], m2 = ps[g][1], m3 = ps[g][2];
            float e1 = ps[g][3], e2 = ps[g][4], e3 = ps[g][5], a = ps[g][6];
            float d = deg + a;
            float pe1 = zpow(d, e1);
            float pe2 = zpow(d, e2);
            float pe3 = zpow(d, e3);
            g_sp2[g][i] = m2 * pe2;
            g_p3 [g][i] = pe3;
            ws += m1 * pe1 + m2 * pe2 * pe3 + m3;
        }
        g_wself[i] = ws;
    }

    __syncthreads();
    #pragma unroll
    for (int off = 1; off < 256; off <<= 1) {
        int t = (tid >= off) ? s[tid - off] : 0;
        __syncthreads();
        s[tid] += t;
        __syncthreads();
    }
    if (i < NN) g_rowptr[i] = s[tid] - v;
    if (tid == 255) g_blk[blockIdx.x] = s[255];
}

__global__ void scan_b_kernel() {
    __shared__ int s[512];
    int tid = threadIdx.x;
    int v = (tid < NB) ? g_blk[tid] : 0;
    s[tid] = v;
    __syncthreads();
    #pragma unroll
    for (int off = 1; off < 512; off <<= 1) {
        int t = (tid >= off) ? s[tid - off] : 0;
        __syncthreads();
        s[tid] += t;
        __syncthreads();
    }
    if (tid < NB) g_blk[tid] = s[tid] - v;
}

__global__ void scan_c_kernel() {
    int i = blockIdx.x * blockDim.x + threadIdx.x;
    if (i < NN) {
        int p = g_rowptr[i] + g_blk[i >> 8];
        g_rowptr[i] = p;
        g_cursor[i] = p;
        if (i == 0) g_rowptr[NN] = EE;
    }
}

__global__ void csr_fill_kernel(const int* __restrict__ row,
                                const int* __restrict__ col) {
    int e = blockIdx.x * blockDim.x + threadIdx.x;
    if (e >= EE) return;
    int r = row[e], c = col[e];
    float w = g_sp2[0][r] * g_p3[0][c] + g_sp2[1][r] * g_p3[1][c];
    int pos = atomicAdd(&g_cursor[r], 1);
    g_ecol[pos] = c;
    g_ew[pos] = w;
}

// ---------------- W -> bf16 split + fragment pack, all 3 layers fused --------
__device__ void wfrag_pack(const float* __restrict__ W, int Ncols,
                           uint2* __restrict__ hi, uint2* __restrict__ lo,
                           int idx) {
    // idx over 8 * (Ncols/8) * 32
    int lane = idx & 31;
    int nt   = (idx >> 5) % (Ncols >> 3);
    int ks   = idx / (32 * (Ncols >> 3));
    int q = lane & 3, g = lane >> 2;
    int n = nt * 8 + g, k0 = ks * 16;
    float w0 = W[(k0 + 2 * q) * Ncols + n];
    float w1 = W[(k0 + 2 * q + 1) * Ncols + n];
    float w2 = W[(k0 + 2 * q + 8) * Ncols + n];
    float w3 = W[(k0 + 2 * q + 9) * Ncols + n];
    float h0 = __bfloat162float(__float2bfloat16(w0));
    float h1 = __bfloat162float(__float2bfloat16(w1));
    float h2 = __bfloat162float(__float2bfloat16(w2));
    float h3 = __bfloat162float(__float2bfloat16(w3));
    hi[idx] = make_uint2(pack_bf2(h0, h1), pack_bf2(h2, h3));
    lo[idx] = make_uint2(pack_bf2(w0 - h0, w1 - h1), pack_bf2(w2 - h2, w3 - h3));
}

__global__ void wconv_all_kernel(const float* __restrict__ W1,
                                 const float* __restrict__ W2,
                                 const float* __restrict__ W3) {
    int i = blockIdx.x * blockDim.x + threadIdx.x;
    const int S128 = 8 * 16 * 32;   // 4096
    const int S64  = 8 *  8 * 32;   // 2048
    if (i < S128)                 wfrag_pack(W1, 128, g_wf1hi, g_wf1lo, i);
    else if (i < 2 * S128)        wfrag_pack(W2, 128, g_wf2hi, g_wf2lo, i - S128);
    else if (i < 2 * S128 + S64)  wfrag_pack(W3,  64, g_wf3hi, g_wf3lo, i - 2 * S128);
}

// ---------------- HMMA GEMM: C[M,BN] = A[M,128] @ W[128,BN] ----------------
// bf16 split precision (3 passes). A in SMEM (hi/lo, padded rows, ldmatrix).
// B fragments loaded directly from pre-packed gmem (L1-resident).
// CTA 128xBN, 8 warps 4(m) x 2(n). 2 CTAs/SM.
template<int BN, bool RELU_IN>
__global__ __launch_bounds__(256, 2) void gemm_mma_kernel(
    const float* __restrict__ A,
    const uint2* __restrict__ Whi, const uint2* __restrict__ Wlo,
    float* __restrict__ C, int M)
{
    constexpr int ASTR = 136;                 // bf16 elems per A row (272 B)
    constexpr int NT   = BN / 16;             // 8-wide n-tiles per warp
    constexpr int NTILES = BN / 8;            // total n-tiles
    constexpr uint32_t O_ALO = 128 * ASTR * 2;
    extern __shared__ char smem[];
    const uint32_t sb = smem_u32(smem);
    const int tid = threadIdx.x;
    const int lane = tid & 31, warp = tid >> 5;
    const int m0 = blockIdx.x * 128;

    // --- A tile: fp32 -> bf16 hi/lo, rows padded to 272B ---
    for (int i = tid; i < 128 * 32; i += 256) {
        int row = i >> 5, q = i & 31;
        float4 v = make_float4(0.f, 0.f, 0.f, 0.f);
        if (m0 + row < M)
            v = *reinterpret_cast<const float4*>(A + (size_t)(m0 + row) * 128 + q * 4);
        if (RELU_IN) {
            v.x = fmaxf(v.x, 0.f); v.y = fmaxf(v.y, 0.f);
            v.z = fmaxf(v.z, 0.f); v.w = fmaxf(v.w, 0.f);
        }
        __nv_bfloat16 hv[4], lv[4];
        hv[0] = __float2bfloat16(v.x); hv[1] = __float2bfloat16(v.y);
        hv[2] = __float2bfloat16(v.z); hv[3] = __float2bfloat16(v.w);
        lv[0] = __float2bfloat16(v.x - __bfloat162float(hv[0]));
        lv[1] = __float2bfloat16(v.y - __bfloat162float(hv[1]));
        lv[2] = __float2bfloat16(v.z - __bfloat162float(hv[2]));
        lv[3] = __float2bfloat16(v.w - __bfloat162float(hv[3]));
        uint32_t off = row * 272 + q * 8;
        *reinterpret_cast<uint2*>(smem + off)         = *reinterpret_cast<uint2*>(hv);
        *reinterpret_cast<uint2*>(smem + O_ALO + off) = *reinterpret_cast<uint2*>(lv);
    }
    __syncthreads();

    // A ldmatrix per-lane address (x4: tile t -> row += (t&1)*8, k += (t>>1)*8)
    const int aRow = (warp >> 1) * 32 + ((lane >> 3) & 1) * 8 + (lane & 7);
    const int aK   = (lane >> 4) * 8;
    const int wn   = warp & 1;                // warp n half

    float acc[2][NT][4];
    #pragma unroll
    for (int mt = 0; mt < 2; mt++)
        #pragma unroll
        for (int nt = 0; nt < NT; nt++)
            #pragma unroll
            for (int j = 0; j < 4; j++) acc[mt][nt][j] = 0.0f;

    #pragma unroll
    for (int pass = 0; pass < 3; pass++) {
        const uint32_t aBase = sb + (pass == 1 ? O_ALO : 0u);
        const uint2* __restrict__ wB = (pass == 2 ? Wlo : Whi);
        #pragma unroll
        for (int ks = 0; ks < 8; ks++) {
            // B fragments: one LDG.64 per n-tile, coalesced per warp
            uint2 b[NT];
            #pragma unroll
            for (int t = 0; t < NT; t++)
                b[t] = wB[((ks * NTILES) + wn * NT + t) * 32 + lane];
            uint32_t a[2][4];
            #pragma unroll
            for (int mt = 0; mt < 2; mt++) {
                uint32_t addr = aBase + ((aRow + mt * 16) * ASTR + ks * 16 + aK) * 2;
                LDSM_X4(a[mt][0], a[mt][1], a[mt][2], a[mt][3], addr);
            }
            #pragma unroll
            for (int mt = 0; mt < 2; mt++)
                #pragma unroll
                for (int nt = 0; nt < NT; nt++)
                    mma16816(acc[mt][nt], a[mt], b[nt].x, b[nt].y);
        }
    }

    // epilogue (C rows padded to NPAD, no guard)
    #pragma unroll
    for (int mt = 0; mt < 2; mt++) {
        int row = m0 + (warp >> 1) * 32 + mt * 16 + (lane >> 2);
        #pragma unroll
        for (int nt = 0; nt < NT; nt++) {
            int colb = wn * (BN / 2) + nt * 8 + (lane & 3) * 2;
            *reinterpret_cast<float2*>(C + (size_t)row * BN + colb) =
                make_float2(acc[mt][nt][0], acc[mt][nt][1]);
            *reinterpret_cast<float2*>(C + (size_t)(row + 8) * BN + colb) =
                make_float2(acc[mt][nt][2], acc[mt][nt][3]);
        }
    }
}

// ---------------- pull aggregation ----------------
__global__ __launch_bounds__(256) void agg_pull128_kernel(
    const float* __restrict__ H, const float* __restrict__ bias,
    float* __restrict__ OUT)
{
    int node = (blockIdx.x * blockDim.x + threadIdx.x) >> 5;
    int lane = threadIdx.x & 31;
    if (node >= NN) return;
    int e = g_rowptr[node];
    int end = g_rowptr[node + 1];

    float4 acc = make_float4(0.f, 0.f, 0.f, 0.f);
    for (; e + 4 <= end; e += 4) {
        int c0 = g_ecol[e], c1 = g_ecol[e + 1], c2 = g_ecol[e + 2], c3 = g_ecol[e + 3];
        float w0 = g_ew[e], w1 = g_ew[e + 1], w2 = g_ew[e + 2], w3 = g_ew[e + 3];
        float4 v0 = reinterpret_cast<const float4*>(H + (size_t)c0 * 128)[lane];
        float4 v1 = reinterpret_cast<const float4*>(H + (size_t)c1 * 128)[lane];
        float4 v2 = reinterpret_cast<const float4*>(H + (size_t)c2 * 128)[lane];
        float4 v3 = reinterpret_cast<const float4*>(H + (size_t)c3 * 128)[lane];
        acc.x = fmaf(w0, v0.x, acc.x); acc.y = fmaf(w0, v0.y, acc.y);
        acc.z = fmaf(w0, v0.z, acc.z); acc.w = fmaf(w0, v0.w, acc.w);
        acc.x = fmaf(w1, v1.x, acc.x); acc.y = fmaf(w1, v1.y, acc.y);
        acc.z = fmaf(w1, v1.z, acc.z); acc.w = fmaf(w1, v1.w, acc.w);
        acc.x = fmaf(w2, v2.x, acc.x); acc.y = fmaf(w2, v2.y, acc.y);
        acc.z = fmaf(w2, v2.z, acc.z); acc.w = fmaf(w2, v2.w, acc.w);
        acc.x = fmaf(w3, v3.x, acc.x); acc.y = fmaf(w3, v3.y, acc.y);
        acc.z = fmaf(w3, v3.z, acc.z); acc.w = fmaf(w3, v3.w, acc.w);
    }
    for (; e < end; e++) {
        int c = g_ecol[e];
        float w = g_ew[e];
        float4 v = reinterpret_cast<const float4*>(H + (size_t)c * 128)[lane];
        acc.x = fmaf(w, v.x, acc.x); acc.y = fmaf(w, v.y, acc.y);
        acc.z = fmaf(w, v.z, acc.z); acc.w = fmaf(w, v.w, acc.w);
    }
    float ws = g_wself[node];
    float4 hs = reinterpret_cast<const float4*>(H + (size_t)node * 128)[lane];
    float4 b  = reinterpret_cast<const float4*>(bias)[lane];
    acc.x = fmaf(ws, hs.x, acc.x) + b.x;
    acc.y = fmaf(ws, hs.y, acc.y) + b.y;
    acc.z = fmaf(ws, hs.z, acc.z) + b.z;
    acc.w = fmaf(ws, hs.w, acc.w) + b.w;
    reinterpret_cast<float4*>(OUT + (size_t)node * 128)[lane] = acc;
}

__global__ __launch_bounds__(256) void agg_pull64_kernel(
    const float* __restrict__ H, const float* __restrict__ bias,
    float* __restrict__ OUT)
{
    int node = (blockIdx.x * blockDim.x + threadIdx.x) >> 5;
    int lane = threadIdx.x & 31;
    if (node >= NN) return;
    int e = g_rowptr[node];
    int end = g_rowptr[node + 1];

    float2 acc = make_float2(0.f, 0.f);
    for (; e + 4 <= end; e += 4) {
        int c0 = g_ecol[e], c1 = g_ecol[e + 1], c2 = g_ecol[e + 2], c3 = g_ecol[e + 3];
        float w0 = g_ew[e], w1 = g_ew[e + 1], w2 = g_ew[e + 2], w3 = g_ew[e + 3];
        float2 v0 = reinterpret_cast<const float2*>(H + (size_t)c0 * 64)[lane];
        float2 v1 = reinterpret_cast<const float2*>(H + (size_t)c1 * 64)[lane];
        float2 v2 = reinterpret_cast<const float2*>(H + (size_t)c2 * 64)[lane];
        float2 v3 = reinterpret_cast<const float2*>(H + (size_t)c3 * 64)[lane];
        acc.x = fmaf(w0, v0.x, acc.x); acc.y = fmaf(w0, v0.y, acc.y);
        acc.x = fmaf(w1, v1.x, acc.x); acc.y = fmaf(w1, v1.y, acc.y);
        acc.x = fmaf(w2, v2.x, acc.x); acc.y = fmaf(w2, v2.y, acc.y);
        acc.x = fmaf(w3, v3.x, acc.x); acc.y = fmaf(w3, v3.y, acc.y);
    }
    for (; e < end; e++) {
        int c = g_ecol[e];
        float w = g_ew[e];
        float2 v = reinterpret_cast<const float2*>(H + (size_t)c * 64)[lane];
        acc.x = fmaf(w, v.x, acc.x); acc.y = fmaf(w, v.y, acc.y);
    }
    float ws = g_wself[node];
    float2 hs = reinterpret_cast<const float2*>(H + (size_t)node * 64)[lane];
    float2 b  = reinterpret_cast<const float2*>(bias)[lane];
    acc.x = fmaf(ws, hs.x, acc.x) + b.x;
    acc.y = fmaf(ws, hs.y, acc.y) + b.y;
    reinterpret_cast<float2*>(OUT + (size_t)node * 64)[lane] = acc;
}

// ---------------- launch ----------------
extern "C" void kernel_launch(void* const* d_in, const int* in_sizes, int n_in,
                              void* d_out, int out_size)
{
    const float* x  = (const float*)d_in[0];
    const int*   ei = (const int*)  d_in[1];
    const float* W1 = (const float*)d_in[2];
    const float* b1 = (const float*)d_in[3];
    const float* W2 = (const float*)d_in[4];
    const float* b2 = (const float*)d_in[5];
    const float* W3 = (const float*)d_in[6];
    const float* b3 = (const float*)d_in[7];
    const float* p1 = (const float*)d_in[8];
    const float* p2 = (const float*)d_in[9];
    const int* row = ei;
    const int* col = ei + EE;
    float* out = (float*)d_out;

    void *h_p, *agg_p;
    cudaGetSymbolAddress(&h_p, g_h);
    cudaGetSymbolAddress(&agg_p, g_agg);
    float* H   = (float*)h_p;
    float* AGG = (float*)agg_p;
    void *w1h, *w1l, *w2h, *w2l, *w3h, *w3l;
    cudaGetSymbolAddress(&w1h, g_wf1hi); cudaGetSymbolAddress(&w1l, g_wf1lo);
    cudaGetSymbolAddress(&w2h, g_wf2hi); cudaGetSymbolAddress(&w2l, g_wf2lo);
    cudaGetSymbolAddress(&w3h, g_wf3hi); cudaGetSymbolAddress(&w3l, g_wf3lo);

    const int TB = 256;
    const int SMA = 2 * (128 * 136 * 2);   // 69632: A hi + lo only
    cudaFuncSetAttribute(gemm_mma_kernel<128, false>, cudaFuncAttributeMaxDynamicSharedMemorySize, SMA);
    cudaFuncSetAttribute(gemm_mma_kernel<128, true>,  cudaFuncAttributeMaxDynamicSharedMemorySize, SMA);
    cudaFuncSetAttribute(gemm_mma_kernel<64,  true>,  cudaFuncAttributeMaxDynamicSharedMemorySize, SMA);

    // prologue: CSR build + W fragment pack (7 launches)
    zero_cnt_kernel<<<(NN + TB - 1) / TB, TB>>>();
    wconv_all_kernel<<<(2 * 4096 + 2048 + TB - 1) / TB, TB>>>(W1, W2, W3);
    deg_count_kernel<<<(EE + TB - 1) / TB, TB>>>(row);
    scan_a_nw_kernel<<<NB, 256>>>(p1, p2);
    scan_b_kernel<<<1, 512>>>();
    scan_c_kernel<<<(NN + TB - 1) / TB, TB>>>();
    csr_fill_kernel<<<(EE + TB - 1) / TB, TB>>>(row, col);

    const int GEMM_BLK = (NN + 127) / 128;
    const int AGG_BLK  = (NN * 32 + TB - 1) / TB;

    // layer 1
    gemm_mma_kernel<128, false><<<GEMM_BLK, TB, SMA>>>(x, (const uint2*)w1h, (const uint2*)w1l, H, NN);
    agg_pull128_kernel<<<AGG_BLK, TB>>>(H, b1, AGG);
    // layer 2
    gemm_mma_kernel<128, true><<<GEMM_BLK, TB, SMA>>>(AGG, (const uint2*)w2h, (const uint2*)w2l, H, NN);
    agg_pull128_kernel<<<AGG_BLK, TB>>>(H, b2, AGG);
    // layer 3 (writes d_out via agg)
    gemm_mma_kernel<64, true><<<GEMM_BLK, TB, SMA>>>(AGG, (const uint2*)w3h, (const uint2*)w3l, H, NN);
    agg_pull64_kernel<<<AGG_BLK, TB>>>(H, b3, out);
}

// round 8
// speedup vs baseline: 1.2371x; 1.2371x over previous
#include <cuda_runtime.h>
#include <cuda_bf16.h>
#include <math.h>
#include <stdint.h>

#define NN 100000
#define EE 1600000
#define NB ((NN + 255) / 256)   // 391 scan blocks
#define NPAD (NN + 128)

// ---------------- scratch (device globals; no allocs allowed) ----------------
__device__ int   g_cnt[NN];
__device__ int   g_rowptr[NN + 1];
__device__ int   g_blk[512];
__device__ int   g_cursor[NN];
__device__ int   g_ecol[EE];
__device__ float g_ew[EE];
__device__ float g_sp2[2][NN];
__device__ float g_p3 [2][NN];
__device__ float g_wself[NN];
__device__ float g_h  [(size_t)NPAD * 128];
__device__ float g_agg[(size_t)NPAD * 128];
// W bf16 split, original [K][N] layout
__device__ __nv_bfloat16 g_w1hi[128 * 128], g_w1lo[128 * 128];
__device__ __nv_bfloat16 g_w2hi[128 * 128], g_w2lo[128 * 128];
__device__ __nv_bfloat16 g_w3hi[128 *  64], g_w3lo[128 *  64];

// ---------------- helpers ----------------
__device__ __forceinline__ uint32_t smem_u32(const void* p) {
    uint32_t a;
    asm("{ .reg .u64 t; cvta.to.shared.u64 t, %1; cvt.u32.u64 %0, t; }" : "=r"(a) : "l"(p));
    return a;
}
__device__ __forceinline__ float zpow(float d, float e) {
    float p = powf(d, e);
    return isinf(p) ? 0.0f : p;
}

#define LDSM_X4(r0, r1, r2, r3, addr)                                          \
    asm volatile("ldmatrix.sync.aligned.m8n8.x4.shared.b16 {%0,%1,%2,%3}, [%4];" \
                 : "=r"(r0), "=r"(r1), "=r"(r2), "=r"(r3) : "r"(addr))
#define LDSM_X4T(r0, r1, r2, r3, addr)                                         \
    asm volatile("ldmatrix.sync.aligned.m8n8.x4.trans.shared.b16 {%0,%1,%2,%3}, [%4];" \
                 : "=r"(r0), "=r"(r1), "=r"(r2), "=r"(r3) : "r"(addr))

__device__ __forceinline__ void mma16816(float* d, const uint32_t* a,
                                         uint32_t b0, uint32_t b1) {
    asm volatile(
        "mma.sync.aligned.m16n8k16.row.col.f32.bf16.bf16.f32 "
        "{%0,%1,%2,%3}, {%4,%5,%6,%7}, {%8,%9}, {%0,%1,%2,%3};"
        : "+f"(d[0]), "+f"(d[1]), "+f"(d[2]), "+f"(d[3])
        : "r"(a[0]), "r"(a[1]), "r"(a[2]), "r"(a[3]), "r"(b0), "r"(b1));
}

// ---------------- GSO / CSR build ----------------
__global__ void zero_cnt_kernel() {
    int i = blockIdx.x * blockDim.x + threadIdx.x;
    if (i < NN) g_cnt[i] = 0;
}

__global__ void deg_count_kernel(const int* __restrict__ row) {
    int e = blockIdx.x * blockDim.x + threadIdx.x;
    if (e < EE) atomicAdd(&g_cnt[row[e]], 1);
}

// fused: block-local exclusive scan of g_cnt AND node GSO weights
__global__ void scan_a_nw_kernel(const float* __restrict__ p1,
                                 const float* __restrict__ p2) {
    __shared__ int s[256];
    int tid = threadIdx.x;
    int i = blockIdx.x * 256 + tid;
    int v = (i < NN) ? g_cnt[i] : 0;
    s[tid] = v;

    if (i < NN) {
        float deg = (float)v;
        float ws = 0.0f;
        const float* ps[2] = {p1, p2};
        #pragma unroll
        for (int g = 0; g < 2; g++) {
            float m1 = ps[g][0], m2 = ps[g][1], m3 = ps[g][2];
            float e1 = ps[g][3], e2 = ps[g][4], e3 = ps[g][5], a = ps[g][6];
            float d = deg + a;
            float pe1 = zpow(d, e1);
            float pe2 = zpow(d, e2);
            float pe3 = zpow(d, e3);
            g_sp2[g][i] = m2 * pe2;
            g_p3 [g][i] = pe3;
            ws += m1 * pe1 + m2 * pe2 * pe3 + m3;
        }
        g_wself[i] = ws;
    }

    __syncthreads();
    #pragma unroll
    for (int off = 1; off < 256; off <<= 1) {
        int t = (tid >= off) ? s[tid - off] : 0;
        __syncthreads();
        s[tid] += t;
        __syncthreads();
    }
    if (i < NN) g_rowptr[i] = s[tid] - v;
    if (tid == 255) g_blk[blockIdx.x] = s[255];
}

__global__ void scan_b_kernel() {
    __shared__ int s[512];
    int tid = threadIdx.x;
    int v = (tid < NB) ? g_blk[tid] : 0;
    s[tid] = v;
    __syncthreads();
    #pragma unroll
    for (int off = 1; off < 512; off <<= 1) {
        int t = (tid >= off) ? s[tid - off] : 0;
        __syncthreads();
        s[tid] += t;
        __syncthreads();
    }
    if (tid < NB) g_blk[tid] = s[tid] - v;
}

__global__ void scan_c_kernel() {
    int i = blockIdx.x * blockDim.x + threadIdx.x;
    if (i < NN) {
        int p = g_rowptr[i] + g_blk[i >> 8];
        g_rowptr[i] = p;
        g_cursor[i] = p;
        if (i == 0) g_rowptr[NN] = EE;
    }
}

__global__ void csr_fill_kernel(const int* __restrict__ row,
                                const int* __restrict__ col) {
    int e = blockIdx.x * blockDim.x + threadIdx.x;
    if (e >= EE) return;
    int r = row[e], c = col[e];
    float w = g_sp2[0][r] * g_p3[0][c] + g_sp2[1][r] * g_p3[1][c];
    int pos = atomicAdd(&g_cursor[r], 1);
    g_ecol[pos] = c;
    g_ew[pos] = w;
}

// ---------------- W bf16 split (layout preserved), all layers in one launch ---
__global__ void wconv_all_kernel(const float* __restrict__ W1,
                                 const float* __restrict__ W2,
                                 const float* __restrict__ W3) {
    int i = blockIdx.x * blockDim.x + threadIdx.x;
    const int S = 128 * 128;
    const float* W; __nv_bfloat16 *hi, *lo; int j;
    if (i < S)                { W = W1; hi = g_w1hi; lo = g_w1lo; j = i; }
    else if (i < 2 * S)       { W = W2; hi = g_w2hi; lo = g_w2lo; j = i - S; }
    else if (i < 2 * S + 128 * 64) { W = W3; hi = g_w3hi; lo = g_w3lo; j = i - 2 * S; }
    else return;
    float w = W[j];
    __nv_bfloat16 h = __float2bfloat16(w);
    hi[j] = h;
    lo[j] = __float2bfloat16(w - __bfloat162float(h));
}

// ---------------- HMMA GEMM: C[M,NC] = A[M,128] @ W[128,NC], 128x64 CTA tile --
// bf16 split precision (3 passes), A + W-slice in SMEM, ldmatrix, 2 CTAs/SM.
// grid.x = M tiles, grid.y = NC/64 column tiles.
template<int NC, bool RELU_IN>
__global__ __launch_bounds__(256, 2) void gemm_mma_kernel(
    const float* __restrict__ A,
    const __nv_bfloat16* __restrict__ Whi, const __nv_bfloat16* __restrict__ Wlo,
    float* __restrict__ C, int M)
{
    constexpr int BN = 64;
    constexpr int ASTR = 136;                 // bf16 elems per A row (272 B)
    constexpr int WSTR = BN + 8;              // 72
    constexpr int NT   = BN / 16;             // 4 n-tiles per warp
    constexpr uint32_t O_ALO = 128 * ASTR * 2;          // 34816
    constexpr uint32_t O_WHI = 2 * O_ALO;               // 69632
    constexpr uint32_t O_WLO = O_WHI + 128 * WSTR * 2;  // 88064
    extern __shared__ char smem[];
    const uint32_t sb = smem_u32(smem);
    const int tid = threadIdx.x;
    const int lane = tid & 31, warp = tid >> 5;
    const int m0 = blockIdx.x * 128;
    const int n0 = blockIdx.y * BN;

    // --- A tile: fp32 -> bf16 hi/lo, rows padded to 272B ---
    for (int i = tid; i < 128 * 32; i += 256) {
        int row = i >> 5, q = i & 31;
        float4 v = make_float4(0.f, 0.f, 0.f, 0.f);
        if (m0 + row < M)
            v = *reinterpret_cast<const float4*>(A + (size_t)(m0 + row) * 128 + q * 4);
        if (RELU_IN) {
            v.x = fmaxf(v.x, 0.f); v.y = fmaxf(v.y, 0.f);
            v.z = fmaxf(v.z, 0.f); v.w = fmaxf(v.w, 0.f);
        }
        __nv_bfloat16 hv[4], lv[4];
        hv[0] = __float2bfloat16(v.x); hv[1] = __float2bfloat16(v.y);
        hv[2] = __float2bfloat16(v.z); hv[3] = __float2bfloat16(v.w);
        lv[0] = __float2bfloat16(v.x - __bfloat162float(hv[0]));
        lv[1] = __float2bfloat16(v.y - __bfloat162float(hv[1]));
        lv[2] = __float2bfloat16(v.z - __bfloat162float(hv[2]));
        lv[3] = __float2bfloat16(v.w - __bfloat162float(hv[3]));
        uint32_t off = row * 272 + q * 8;
        *reinterpret_cast<uint2*>(smem + off)         = *reinterpret_cast<uint2*>(hv);
        *reinterpret_cast<uint2*>(smem + O_ALO + off) = *reinterpret_cast<uint2*>(lv);
    }
    // --- W slice: [128][64] bf16 hi/lo from column window n0 ---
    for (int i = tid; i < 128 * (BN / 8); i += 256) {
        int row = i >> 3, q = i & 7;
        uint32_t off = row * (WSTR * 2) + q * 16;
        *reinterpret_cast<uint4*>(smem + O_WHI + off) =
            *reinterpret_cast<const uint4*>(Whi + row * NC + n0 + q * 8);
        *reinterpret_cast<uint4*>(smem + O_WLO + off) =
            *reinterpret_cast<const uint4*>(Wlo + row * NC + n0 + q * 8);
    }
    __syncthreads();

    // A (non-trans x4): tile t -> row += (t&1)*8, k += (t>>1)*8
    const int aRow = (warp >> 1) * 32 + ((lane >> 3) & 1) * 8 + (lane & 7);
    const int aK   = (lane >> 4) * 8;
    // B (trans x4): tile t -> k += (t&1)*8, n += (t>>1)*8
    const int bK = ((lane >> 3) & 1) * 8 + (lane & 7);
    const int bN = (warp & 1) * (BN / 2) + (lane >> 4) * 8;

    float acc[2][NT][4];
    #pragma unroll
    for (int mt = 0; mt < 2; mt++)
        #pragma unroll
        for (int nt = 0; nt < NT; nt++)
            #pragma unroll
            for (int j = 0; j < 4; j++) acc[mt][nt][j] = 0.0f;

    #pragma unroll
    for (int pass = 0; pass < 3; pass++) {
        const uint32_t aBase = sb + (pass == 1 ? O_ALO : 0u);
        const uint32_t wBase = sb + (pass == 2 ? O_WLO : O_WHI);
        #pragma unroll
        for (int k0 = 0; k0 < 128; k0 += 16) {
            uint32_t a[2][4];
            #pragma unroll
            for (int mt = 0; mt < 2; mt++) {
                uint32_t addr = aBase + ((aRow + mt * 16) * ASTR + k0 + aK) * 2;
                LDSM_X4(a[mt][0], a[mt][1], a[mt][2], a[mt][3], addr);
            }
            uint32_t b[NT / 2][4];
            #pragma unroll
            for (int np = 0; np < NT / 2; np++) {
                uint32_t addr = wBase + ((k0 + bK) * WSTR + bN + np * 16) * 2;
                LDSM_X4T(b[np][0], b[np][1], b[np][2], b[np][3], addr);
            }
            #pragma unroll
            for (int mt = 0; mt < 2; mt++)
                #pragma unroll
                for (int nt = 0; nt < NT; nt++)
                    mma16816(acc[mt][nt], a[mt],
                             b[nt >> 1][(nt & 1) * 2], b[nt >> 1][(nt & 1) * 2 + 1]);
        }
    }

    // epilogue (C rows padded to NPAD, no guard)
    #pragma unroll
    for (int mt = 0; mt < 2; mt++) {
        int row = m0 + (warp >> 1) * 32 + mt * 16 + (lane >> 2);
        #pragma unroll
        for (int nt = 0; nt < NT; nt++) {
            int colb = n0 + (warp & 1) * (BN / 2) + nt * 8 + (lane & 3) * 2;
            *reinterpret_cast<float2*>(C + (size_t)row * NC + colb) =
                make_float2(acc[mt][nt][0], acc[mt][nt][1]);
            *reinterpret_cast<float2*>(C + (size_t)(row + 8) * NC + colb) =
                make_float2(acc[mt][nt][2], acc[mt][nt][3]);
        }
    }
}

// ---------------- pull aggregation ----------------
__global__ __launch_bounds__(256) void agg_pull128_kernel(
    const float* __restrict__ H, const float* __restrict__ bias,
    float* __restrict__ OUT)
{
    int node = (blockIdx.x * blockDim.x + threadIdx.x) >> 5;
    int lane = threadIdx.x & 31;
    if (node >= NN) return;
    int e = g_rowptr[node];
    int end = g_rowptr[node + 1];

    float4 acc = make_float4(0.f, 0.f, 0.f, 0.f);
    for (; e + 4 <= end; e += 4) {
        int c0 = g_ecol[e], c1 = g_ecol[e + 1], c2 = g_ecol[e + 2], c3 = g_ecol[e + 3];
        float w0 = g_ew[e], w1 = g_ew[e + 1], w2 = g_ew[e + 2], w3 = g_ew[e + 3];
        float4 v0 = reinterpret_cast<const float4*>(H + (size_t)c0 * 128)[lane];
        float4 v1 = reinterpret_cast<const float4*>(H + (size_t)c1 * 128)[lane];
        float4 v2 = reinterpret_cast<const float4*>(H + (size_t)c2 * 128)[lane];
        float4 v3 = reinterpret_cast<const float4*>(H + (size_t)c3 * 128)[lane];
        acc.x = fmaf(w0, v0.x, acc.x); acc.y = fmaf(w0, v0.y, acc.y);
        acc.z = fmaf(w0, v0.z, acc.z); acc.w = fmaf(w0, v0.w, acc.w);
        acc.x = fmaf(w1, v1.x, acc.x); acc.y = fmaf(w1, v1.y, acc.y);
        acc.z = fmaf(w1, v1.z, acc.z); acc.w = fmaf(w1, v1.w, acc.w);
        acc.x = fmaf(w2, v2.x, acc.x); acc.y = fmaf(w2, v2.y, acc.y);
        acc.z = fmaf(w2, v2.z, acc.z); acc.w = fmaf(w2, v2.w, acc.w);
        acc.x = fmaf(w3, v3.x, acc.x); acc.y = fmaf(w3, v3.y, acc.y);
        acc.z = fmaf(w3, v3.z, acc.z); acc.w = fmaf(w3, v3.w, acc.w);
    }
    for (; e < end; e++) {
        int c = g_ecol[e];
        float w = g_ew[e];
        float4 v = reinterpret_cast<const float4*>(H + (size_t)c * 128)[lane];
        acc.x = fmaf(w, v.x, acc.x); acc.y = fmaf(w, v.y, acc.y);
        acc.z = fmaf(w, v.z, acc.z); acc.w = fmaf(w, v.w, acc.w);
    }
    float ws = g_wself[node];
    float4 hs = reinterpret_cast<const float4*>(H + (size_t)node * 128)[lane];
    float4 b  = reinterpret_cast<const float4*>(bias)[lane];
    acc.x = fmaf(ws, hs.x, acc.x) + b.x;
    acc.y = fmaf(ws, hs.y, acc.y) + b.y;
    acc.z = fmaf(ws, hs.z, acc.z) + b.z;
    acc.w = fmaf(ws, hs.w, acc.w) + b.w;
    reinterpret_cast<float4*>(OUT + (size_t)node * 128)[lane] = acc;
}

__global__ __launch_bounds__(256) void agg_pull64_kernel(
    const float* __restrict__ H, const float* __restrict__ bias,
    float* __restrict__ OUT)
{
    int node = (blockIdx.x * blockDim.x + threadIdx.x) >> 5;
    int lane = threadIdx.x & 31;
    if (node >= NN) return;
    int e = g_rowptr[node];
    int end = g_rowptr[node + 1];

    float2 acc = make_float2(0.f, 0.f);
    for (; e + 4 <= end; e += 4) {
        int c0 = g_ecol[e], c1 = g_ecol[e + 1], c2 = g_ecol[e + 2], c3 = g_ecol[e + 3];
        float w0 = g_ew[e], w1 = g_ew[e + 1], w2 = g_ew[e + 2], w3 = g_ew[e + 3];
        float2 v0 = reinterpret_cast<const float2*>(H + (size_t)c0 * 64)[lane];
        float2 v1 = reinterpret_cast<const float2*>(H + (size_t)c1 * 64)[lane];
        float2 v2 = reinterpret_cast<const float2*>(H + (size_t)c2 * 64)[lane];
        float2 v3 = reinterpret_cast<const float2*>(H + (size_t)c3 * 64)[lane];
        acc.x = fmaf(w0, v0.x, acc.x); acc.y = fmaf(w0, v0.y, acc.y);
        acc.x = fmaf(w1, v1.x, acc.x); acc.y = fmaf(w1, v1.y, acc.y);
        acc.x = fmaf(w2, v2.x, acc.x); acc.y = fmaf(w2, v2.y, acc.y);
        acc.x = fmaf(w3, v3.x, acc.x); acc.y = fmaf(w3, v3.y, acc.y);
    }
    for (; e < end; e++) {
        int c = g_ecol[e];
        float w = g_ew[e];
        float2 v = reinterpret_cast<const float2*>(H + (size_t)c * 64)[lane];
        acc.x = fmaf(w, v.x, acc.x); acc.y = fmaf(w, v.y, acc.y);
    }
    float ws = g_wself[node];
    float2 hs = reinterpret_cast<const float2*>(H + (size_t)node * 64)[lane];
    float2 b  = reinterpret_cast<const float2*>(bias)[lane];
    acc.x = fmaf(ws, hs.x, acc.x) + b.x;
    acc.y = fmaf(ws, hs.y, acc.y) + b.y;
    reinterpret_cast<float2*>(OUT + (size_t)node * 64)[lane] = acc;
}

// ---------------- launch ----------------
extern "C" void kernel_launch(void* const* d_in, const int* in_sizes, int n_in,
                              void* d_out, int out_size)
{
    const float* x  = (const float*)d_in[0];
    const int*   ei = (const int*)  d_in[1];
    const float* W1 = (const float*)d_in[2];
    const float* b1 = (const float*)d_in[3];
    const float* W2 = (const float*)d_in[4];
    const float* b2 = (const float*)d_in[5];
    const float* W3 = (const float*)d_in[6];
    const float* b3 = (const float*)d_in[7];
    const float* p1 = (const float*)d_in[8];
    const float* p2 = (const float*)d_in[9];
    const int* row = ei;
    const int* col = ei + EE;
    float* out = (float*)d_out;

    void *h_p, *agg_p;
    cudaGetSymbolAddress(&h_p, g_h);
    cudaGetSymbolAddress(&agg_p, g_agg);
    float* H   = (float*)h_p;
    float* AGG = (float*)agg_p;
    void *w1h, *w1l, *w2h, *w2l, *w3h, *w3l;
    cudaGetSymbolAddress(&w1h, g_w1hi); cudaGetSymbolAddress(&w1l, g_w1lo);
    cudaGetSymbolAddress(&w2h, g_w2hi); cudaGetSymbolAddress(&w2l, g_w2lo);
    cudaGetSymbolAddress(&w3h, g_w3hi); cudaGetSymbolAddress(&w3l, g_w3lo);

    const int TB = 256;
    const int SMA = 2 * (128 * 136 * 2) + 2 * (128 * 72 * 2);   // 106496
    cudaFuncSetAttribute(gemm_mma_kernel<128, false>, cudaFuncAttributeMaxDynamicSharedMemorySize, SMA);
    cudaFuncSetAttribute(gemm_mma_kernel<128, true>,  cudaFuncAttributeMaxDynamicSharedMemorySize, SMA);
    cudaFuncSetAttribute(gemm_mma_kernel<64,  true>,  cudaFuncAttributeMaxDynamicSharedMemorySize, SMA);

    // prologue: CSR build + W split (7 launches)
    zero_cnt_kernel<<<(NN + TB - 1) / TB, TB>>>();
    wconv_all_kernel<<<(2 * 128 * 128 + 128 * 64 + TB - 1) / TB, TB>>>(W1, W2, W3);
    deg_count_kernel<<<(EE + TB - 1) / TB, TB>>>(row);
    scan_a_nw_kernel<<<NB, 256>>>(p1, p2);
    scan_b_kernel<<<1, 512>>>();
    scan_c_kernel<<<(NN + TB - 1) / TB, TB>>>();
    csr_fill_kernel<<<(EE + TB - 1) / TB, TB>>>(row, col);

    const int GEMM_BLK = (NN + 127) / 128;   // 782
    const int AGG_BLK  = (NN * 32 + TB - 1) / TB;

    // layer 1
    gemm_mma_kernel<128, false><<<dim3(GEMM_BLK, 2), TB, SMA>>>(
        x, (const __nv_bfloat16*)w1h, (const __nv_bfloat16*)w1l, H, NN);
    agg_pull128_kernel<<<AGG_BLK, TB>>>(H, b1, AGG);
    // layer 2
    gemm_mma_kernel<128, true><<<dim3(GEMM_BLK, 2), TB, SMA>>>(
        AGG, (const __nv_bfloat16*)w2h, (const __nv_bfloat16*)w2l, H, NN);
    agg_pull128_kernel<<<AGG_BLK, TB>>>(H, b2, AGG);
    // layer 3 (writes d_out via agg)
    gemm_mma_kernel<64, true><<<dim3(GEMM_BLK, 1), TB, SMA>>>(
        AGG, (const __nv_bfloat16*)w3h, (const __nv_bfloat16*)w3l, H, NN);
    agg_pull64_kernel<<<AGG_BLK, TB>>>(H, b3, out);
}